// round 3
// baseline (speedup 1.0000x reference)
#include <cuda_runtime.h>
#include <cuda_bf16.h>

#define BB       4096
#define VOCABN   50000
#define FF       64
#define K_PAD    50176
#define K_SPLITS 8
#define K_PER    6272
#define ITERS    98          // K_PER / 64
#define M_TILES  32
#define NB       72          // B n-rows: 64 V cols + 1 c col + 7 zero pad
#define BROW     72          // smem k-stride in bf16 (64 data + 8 pad) = 144B

// ---- device-global scratch (zero-initialized at load; rows 65..71 of B stay 0) ----
__device__ __align__(16) __nv_bfloat16 g_Bhi[NB * K_PAD];
__device__ __align__(16) __nv_bfloat16 g_Blo[NB * K_PAD];
__device__ float g_xv[BB * FF];
__device__ float g_xc[BB];

__device__ __forceinline__ void cp16(void* dst, const void* src) {
    unsigned d = (unsigned)__cvta_generic_to_shared(dst);
    asm volatile("cp.async.cg.shared.global [%0], [%1], 16;" :: "r"(d), "l"(src));
}
__device__ __forceinline__ void mma16816(float* d, const unsigned* a, const unsigned* b) {
    asm volatile(
        "mma.sync.aligned.m16n8k16.row.col.f32.bf16.bf16.f32 "
        "{%0,%1,%2,%3}, {%4,%5,%6,%7}, {%8,%9}, {%0,%1,%2,%3};"
        : "+f"(d[0]), "+f"(d[1]), "+f"(d[2]), "+f"(d[3])
        : "r"(a[0]), "r"(a[1]), "r"(a[2]), "r"(a[3]), "r"(b[0]), "r"(b[1]));
}

// ---------------- zero per-launch scratch ----------------
__global__ void fm_zero() {
    int i = blockIdx.x * blockDim.x + threadIdx.x;
    if (i < BB * FF) g_xv[i] = 0.f;
    if (i < BB)      g_xc[i] = 0.f;
}

// ---------------- preprocess: B = [V | bias-0.5*||v||^2 | 0] in hi/lo bf16, K-major ----------------
__global__ void fm_prep(const float* __restrict__ V, const float* __restrict__ bias) {
    __shared__ float sm[64][65];
    __shared__ float cs[64];
    int i0 = blockIdx.x * 64;
    int tid = threadIdx.x;
    for (int idx = tid; idx < 64 * 64; idx += 256) {
        int i = idx >> 6, f = idx & 63;
        int gi = i0 + i;
        sm[i][f] = (gi < VOCABN) ? V[(size_t)gi * 64 + f] : 0.f;
    }
    __syncthreads();
    if (tid < 64) {
        float s = 0.f;
        #pragma unroll
        for (int f = 0; f < 64; f++) { float v = sm[tid][f]; s += v * v; }
        int gi = i0 + tid;
        float b = (gi < VOCABN) ? bias[gi] : 0.f;
        cs[tid] = b - 0.5f * s;
    }
    __syncthreads();
    for (int idx = tid; idx < 64 * 64; idx += 256) {
        int f = idx >> 6, i = idx & 63;
        float v = sm[i][f];
        __nv_bfloat16 h = __float2bfloat16(v);
        __nv_bfloat16 l = __float2bfloat16(v - __bfloat162float(h));
        g_Bhi[(size_t)f * K_PAD + i0 + i] = h;
        g_Blo[(size_t)f * K_PAD + i0 + i] = l;
    }
    if (tid < 64) {
        float v = cs[tid];
        __nv_bfloat16 h = __float2bfloat16(v);
        __nv_bfloat16 l = __float2bfloat16(v - __bfloat162float(h));
        g_Bhi[(size_t)64 * K_PAD + i0 + tid] = h;
        g_Blo[(size_t)64 * K_PAD + i0 + tid] = l;
    }
}

// ---------------- main: split-K GEMM, A gmem->reg, B cp.async double-buffered ----------------
__global__ void __launch_bounds__(256, 2) fm_main(const int* __restrict__ x) {
    __shared__ __align__(16) __nv_bfloat16 sB[2][2][NB][BROW];   // [stage][limb][n][k] 41.5KB

    const int tid  = threadIdx.x;
    const int w    = tid >> 5;
    const int lane = tid & 31;
    const int gid  = lane >> 2;
    const int tid4 = lane & 3;
    const int mt   = blockIdx.x & (M_TILES - 1);
    const int ks   = blockIdx.x >> 5;
    const int m0   = mt * 128;
    const int k0   = ks * K_PER;
    const int row0 = m0 + w * 16 + gid;

    const int* xr0 = x + (size_t)row0 * VOCABN;
    const int* xr8 = xr0 + (size_t)8 * VOCABN;

    float acc[9][4];
    #pragma unroll
    for (int n = 0; n < 9; n++)
        #pragma unroll
        for (int i = 0; i < 4; i++) acc[n][i] = 0.f;

    // stage one K=64 tile of both limbs: 2 * 72 rows * 8 chunks(16B) = 1152 chunks
    auto stageB = [&](int st, int k) {
        #pragma unroll
        for (int j = 0; j < 5; j++) {
            int c = tid + j * 256;
            if (c < 1152) {
                int limb = (c >= 576) ? 1 : 0;
                int cc = c - limb * 576;
                int n = cc >> 3, ch = cc & 7;
                const __nv_bfloat16* g = limb ? g_Blo : g_Bhi;
                cp16(&sB[st][limb][n][ch * 8], g + (size_t)n * K_PAD + k + ch * 8);
            }
        }
        asm volatile("cp.async.commit_group;");
    };

    stageB(0, k0);

    for (int it = 0; it < ITERS; it++) {
        const int p = it & 1;
        if (it + 1 < ITERS) {
            stageB(p ^ 1, k0 + (it + 1) * 64);
            asm volatile("cp.async.wait_group 1;");
        } else {
            asm volatile("cp.async.wait_group 0;");
        }
        __syncthreads();

        // ---- A: 16 int2 of {0,1} for this warp's 16 rows x 64 k ----
        const int kk = k0 + it * 64;
        int2 raw[16];
        #pragma unroll
        for (int s2 = 0; s2 < 4; s2++) {
            int c0 = kk + s2 * 16 + tid4 * 2;
            int c8 = c0 + 8;
            raw[s2*4+0] = (c0 < VOCABN) ? *(const int2*)(xr0 + c0) : make_int2(0, 0);
            raw[s2*4+1] = (c0 < VOCABN) ? *(const int2*)(xr8 + c0) : make_int2(0, 0);
            raw[s2*4+2] = (c8 < VOCABN) ? *(const int2*)(xr0 + c8) : make_int2(0, 0);
            raw[s2*4+3] = (c8 < VOCABN) ? *(const int2*)(xr8 + c8) : make_int2(0, 0);
        }

        #pragma unroll
        for (int s2 = 0; s2 < 4; s2++) {
            unsigned a[4];
            #pragma unroll
            for (int q = 0; q < 4; q++) {
                int2 v = raw[s2 * 4 + q];
                a[q] = ((unsigned)v.x + ((unsigned)v.y << 16)) * 0x3F80u;  // {0,1}x2 -> bf16x2
            }
            const int kb = s2 * 16 + tid4 * 2;
            #pragma unroll
            for (int limb = 0; limb < 2; limb++) {
                #pragma unroll
                for (int nf = 0; nf < 9; nf++) {
                    const __nv_bfloat16* bp = &sB[p][limb][nf * 8 + gid][kb];
                    unsigned b[2];
                    b[0] = *(const unsigned*)bp;
                    b[1] = *(const unsigned*)(bp + 8);
                    mma16816(acc[nf], a, b);
                }
            }
        }
        __syncthreads();   // all warps done reading stage p before it's overwritten
    }

    // ---- epilogue: split-K accumulate into global scratch ----
    float* xv0 = &g_xv[(size_t)row0 * FF];
    float* xv8 = xv0 + 8 * FF;
    #pragma unroll
    for (int nf = 0; nf < 8; nf++) {
        int col = nf * 8 + tid4 * 2;
        atomicAdd(xv0 + col,     acc[nf][0]);
        atomicAdd(xv0 + col + 1, acc[nf][1]);
        atomicAdd(xv8 + col,     acc[nf][2]);
        atomicAdd(xv8 + col + 1, acc[nf][3]);
    }
    if (tid4 == 0) {   // c column (n = 64)
        atomicAdd(&g_xc[row0],     acc[8][0]);
        atomicAdd(&g_xc[row0 + 8], acc[8][2]);
    }
}

// ---------------- finalize: out = g_bias + xc + 0.5 * ||xv||^2 ----------------
__global__ void fm_fin(const float* __restrict__ gb, float* __restrict__ out) {
    int b = blockIdx.x * blockDim.x + threadIdx.x;
    if (b >= BB) return;
    const float4* v = (const float4*)&g_xv[(size_t)b * FF];
    float ss = 0.f;
    #pragma unroll
    for (int i = 0; i < 16; i++) {
        float4 t = v[i];
        ss += t.x * t.x + t.y * t.y + t.z * t.z + t.w * t.w;
    }
    out[b] = gb[0] + g_xc[b] + 0.5f * ss;
}

extern "C" void kernel_launch(void* const* d_in, const int* in_sizes, int n_in,
                              void* d_out, int out_size) {
    const int*   x    = (const int*)d_in[0];
    const float* V    = (const float*)d_in[1];
    const float* bias = (const float*)d_in[2];
    const float* gb   = (const float*)d_in[3];
    float* out = (float*)d_out;
    (void)in_sizes; (void)n_in; (void)out_size;

    fm_zero<<<(BB * FF + 255) / 256, 256>>>();
    fm_prep<<<K_PAD / 64, 256>>>(V, bias);
    fm_main<<<M_TILES * K_SPLITS, 256>>>(x);
    fm_fin<<<(BB + 255) / 256, 256>>>(gb, out);
}

// round 5
// speedup vs baseline: 1.0934x; 1.0934x over previous
#include <cuda_runtime.h>
#include <cuda_bf16.h>

#define BB       4096
#define VOCABN   50000
#define FF       64
#define K_PAD    50176
#define K_SPLITS 8
#define K_PER    6272
#define ITERS    98          // K_PER / 64
#define M_TILES  32
#define NB       72          // 64 V cols + 1 c col + 7 zero pad
#define BROW     72          // smem k-stride in bf16 (64 data + 8 pad) = 144B
#define LIMB_B   (NB * BROW * 2)    // 10368 bytes per limb per stage

// ---- device-global scratch (zero-initialized; B rows 65..71 stay 0) ----
__device__ __align__(16) __nv_bfloat16 g_Bhi[NB * K_PAD];
__device__ __align__(16) __nv_bfloat16 g_Blo[NB * K_PAD];
__device__ float g_xv[BB * FF];
__device__ float g_xc[BB];

__device__ __forceinline__ unsigned s2u(const void* p) {
    return (unsigned)__cvta_generic_to_shared(p);
}
__device__ __forceinline__ void cp16(void* dst, const void* src) {
    asm volatile("cp.async.cg.shared.global [%0], [%1], 16;"
                 :: "r"(s2u(dst)), "l"(src));
}
__device__ __forceinline__ void ldsm4(unsigned* r, unsigned addr) {
    asm volatile("ldmatrix.sync.aligned.m8n8.x4.shared.b16 {%0,%1,%2,%3}, [%4];"
                 : "=r"(r[0]), "=r"(r[1]), "=r"(r[2]), "=r"(r[3]) : "r"(addr));
}
__device__ __forceinline__ void mma16816(float* d, const unsigned* a, const unsigned* b) {
    asm volatile(
        "mma.sync.aligned.m16n8k16.row.col.f32.bf16.bf16.f32 "
        "{%0,%1,%2,%3}, {%4,%5,%6,%7}, {%8,%9}, {%0,%1,%2,%3};"
        : "+f"(d[0]), "+f"(d[1]), "+f"(d[2]), "+f"(d[3])
        : "r"(a[0]), "r"(a[1]), "r"(a[2]), "r"(a[3]), "r"(b[0]), "r"(b[1]));
}

// ---------------- zero per-launch scratch ----------------
__global__ void fm_zero() {
    int i = blockIdx.x * blockDim.x + threadIdx.x;
    if (i < BB * FF) g_xv[i] = 0.f;
    if (i < BB)      g_xc[i] = 0.f;
}

// ---------------- preprocess: B = [V | bias-0.5*||v||^2 | 0] hi/lo bf16, K-major ----------------
__global__ void fm_prep(const float* __restrict__ V, const float* __restrict__ bias) {
    __shared__ float sm[64][65];
    __shared__ float cs[64];
    int i0 = blockIdx.x * 64;
    int tid = threadIdx.x;
    for (int idx = tid; idx < 64 * 64; idx += 256) {
        int i = idx >> 6, f = idx & 63;
        int gi = i0 + i;
        sm[i][f] = (gi < VOCABN) ? V[(size_t)gi * 64 + f] : 0.f;
    }
    __syncthreads();
    if (tid < 64) {
        float s = 0.f;
        #pragma unroll
        for (int f = 0; f < 64; f++) { float v = sm[tid][f]; s += v * v; }
        int gi = i0 + tid;
        float b = (gi < VOCABN) ? bias[gi] : 0.f;
        cs[tid] = b - 0.5f * s;
    }
    __syncthreads();
    for (int idx = tid; idx < 64 * 64; idx += 256) {
        int f = idx >> 6, i = idx & 63;
        float v = sm[i][f];
        __nv_bfloat16 h = __float2bfloat16(v);
        __nv_bfloat16 l = __float2bfloat16(v - __bfloat162float(h));
        g_Bhi[(size_t)f * K_PAD + i0 + i] = h;
        g_Blo[(size_t)f * K_PAD + i0 + i] = l;
    }
    if (tid < 64) {
        float v = cs[tid];
        __nv_bfloat16 h = __float2bfloat16(v);
        __nv_bfloat16 l = __float2bfloat16(v - __bfloat162float(h));
        g_Bhi[(size_t)64 * K_PAD + i0 + tid] = h;
        g_Blo[(size_t)64 * K_PAD + i0 + tid] = l;
    }
}

// ---------------- main: split-K GEMM; m32 warps, A reg-pipelined, B ldmatrix ----------------
__global__ void __launch_bounds__(128, 3) fm_main(const int* __restrict__ x) {
    __shared__ __align__(16) __nv_bfloat16 sB[2][2][NB][BROW];   // 41.5KB

    const int tid  = threadIdx.x;
    const int w    = tid >> 5;
    const int lane = tid & 31;
    const int gid  = lane >> 2;
    const int t2   = (lane & 3) * 2;
    const int mt   = blockIdx.x & (M_TILES - 1);
    const int ks   = blockIdx.x >> 5;
    const int m0   = mt * 128;
    const int k0   = ks * K_PER;

    // 4 row pointers for this lane (warp covers 32 rows)
    const int* xr[4];
    bool nl[4];
    #pragma unroll
    for (int j = 0; j < 4; j++) {
        int r = m0 + w * 32 + j * 8 + gid;
        xr[j] = x + (size_t)r * VOCABN;
        nl[j] = (r != BB - 1);
    }

    float acc[9][2][4];
    #pragma unroll
    for (int n = 0; n < 9; n++)
        #pragma unroll
        for (int m = 0; m < 2; m++)
            #pragma unroll
            for (int i = 0; i < 4; i++) acc[n][m][i] = 0.f;

    // stage one K=64 B tile (both limbs): 2*72*8 = 1152 16B chunks, 9/thread
    auto stageB = [&](int st, int k) {
        #pragma unroll
        for (int j = 0; j < 9; j++) {
            int c = tid + j * 128;
            int limb = (c >= 576) ? 1 : 0;
            int cc = c - limb * 576;
            int n = cc >> 3, ch = cc & 7;
            const __nv_bfloat16* g = limb ? g_Blo : g_Bhi;
            cp16(&sB[st][limb][n][ch * 8], g + (size_t)n * K_PAD + k + ch * 8);
        }
        asm volatile("cp.async.commit_group;");
    };

    // A: load 16 int2 for one k32 half (rows {gid,+8,+16,+24} x k offsets)
    int2 raw[16];
    unsigned pa[16];    // packed a-frags: [(mf*2+s2)*4 + q]
    auto loadA = [&](int cb) {
        #pragma unroll
        for (int mf = 0; mf < 2; mf++)
            #pragma unroll
            for (int s2 = 0; s2 < 2; s2++)
                #pragma unroll
                for (int q = 0; q < 4; q++) {
                    const int* p = xr[mf * 2 + (q & 1)];
                    int c = cb + s2 * 16 + (q >> 1) * 8 + t2;
                    bool ok = nl[mf * 2 + (q & 1)] | (c < VOCABN);
                    raw[(mf * 2 + s2) * 4 + q] = ok ? *(const int2*)(p + c)
                                                    : make_int2(0, 0);
                }
    };
    auto packA = [&]() {
        #pragma unroll
        for (int i = 0; i < 16; i++)
            pa[i] = ((unsigned)raw[i].x + ((unsigned)raw[i].y << 16)) * 0x3F80u;
    };

    const unsigned sm_lane = (unsigned)((lane & 7) * 144 + (lane >> 3) * 16);
    const unsigned sb0 = s2u(&sB[0][0][0][0]);

    stageB(0, k0);
    loadA(k0);
    packA();

    for (int it = 0; it < ITERS; it++) {
        const int p = it & 1;
        __syncthreads();                       // prior reads of stage p^1 done
        if (it + 1 < ITERS) {
            stageB(p ^ 1, k0 + (it + 1) * 64);
            asm volatile("cp.async.wait_group 1;");
        } else {
            asm volatile("cp.async.wait_group 0;");
        }
        __syncthreads();                       // stage p visible to all warps

        const unsigned stbase = sb0 + (unsigned)p * (2 * LIMB_B) + sm_lane;
        #pragma unroll
        for (int half = 0; half < 2; half++) {
            // prefetch next half's A during this half's MMAs
            loadA(k0 + it * 64 + 32 + half * 32);
            #pragma unroll
            for (int limb = 0; limb < 2; limb++) {
                const unsigned lb = stbase + (unsigned)limb * LIMB_B + half * 64;
                #pragma unroll
                for (int nf = 0; nf < 9; nf++) {
                    unsigned bm[4];
                    ldsm4(bm, lb + (unsigned)nf * (8 * 144));
                    #pragma unroll
                    for (int s2 = 0; s2 < 2; s2++)
                        #pragma unroll
                        for (int mf = 0; mf < 2; mf++)
                            mma16816(acc[nf][mf], &pa[(mf * 2 + s2) * 4], &bm[s2 * 2]);
                }
            }
            packA();
        }
    }

    // ---- epilogue: split-K accumulate ----
    #pragma unroll
    for (int mf = 0; mf < 2; mf++) {
        int rowA = m0 + w * 32 + mf * 16 + gid;
        float* xvA = &g_xv[(size_t)rowA * FF];
        float* xvB = xvA + 8 * FF;
        #pragma unroll
        for (int nf = 0; nf < 8; nf++) {
            int col = nf * 8 + t2;
            atomicAdd(xvA + col,     acc[nf][mf][0]);
            atomicAdd(xvA + col + 1, acc[nf][mf][1]);
            atomicAdd(xvB + col,     acc[nf][mf][2]);
            atomicAdd(xvB + col + 1, acc[nf][mf][3]);
        }
        if (t2 == 0) {   // c column (n = 64)
            atomicAdd(&g_xc[rowA],     acc[8][mf][0]);
            atomicAdd(&g_xc[rowA + 8], acc[8][mf][2]);
        }
    }
}

// ---------------- finalize: out = g_bias + xc + 0.5 * ||xv||^2 ----------------
__global__ void fm_fin(const float* __restrict__ gb, float* __restrict__ out) {
    int b = blockIdx.x * blockDim.x + threadIdx.x;
    if (b >= BB) return;
    const float4* v = (const float4*)&g_xv[(size_t)b * FF];
    float ss = 0.f;
    #pragma unroll
    for (int i = 0; i < 16; i++) {
        float4 t = v[i];
        ss += t.x * t.x + t.y * t.y + t.z * t.z + t.w * t.w;
    }
    out[b] = gb[0] + g_xc[b] + 0.5f * ss;
}

extern "C" void kernel_launch(void* const* d_in, const int* in_sizes, int n_in,
                              void* d_out, int out_size) {
    const int*   x    = (const int*)d_in[0];
    const float* V    = (const float*)d_in[1];
    const float* bias = (const float*)d_in[2];
    const float* gb   = (const float*)d_in[3];
    float* out = (float*)d_out;
    (void)in_sizes; (void)n_in; (void)out_size;

    fm_zero<<<(BB * FF + 255) / 256, 256>>>();
    fm_prep<<<K_PAD / 64, 256>>>(V, bias);
    fm_main<<<M_TILES * K_SPLITS, 128>>>(x);
    fm_fin<<<(BB + 255) / 256, 256>>>(gb, out);
}

// round 6
// speedup vs baseline: 1.4680x; 1.3427x over previous
#include <cuda_runtime.h>

#define BB       4096
#define VOCABN   50000
#define FF       64
#define K_PAD    50688       // 9 * 5632, B zero-padded beyond 50000
#define K_SPLITS 9
#define K_PER    5632        // 44 * 128
#define ITERS    44
#define TILE_K   128
#define M_TILES  32
#define NB       72          // 64 V cols + 1 c col + 7 zero pad
#define BROW8    144         // int8 smem row stride (128 data + 16 pad), 16B-aligned, conflict-free
#define LIMB_B   (NB * BROW8)   // 10368 bytes per limb per stage

// ---- device-global scratch (zero-initialized; B rows 65..71 stay 0) ----
__device__ __align__(16) signed char g_Bh8[NB * K_PAD];
__device__ __align__(16) signed char g_Bl8[NB * K_PAD];
__device__ float g_xv[BB * FF];
__device__ float g_xc[BB];
__device__ int   g_maxb[65];     // per-column max |B| as float bits (non-negative -> int monotone)
__device__ float g_s[65];
__device__ float g_inv[65];

__device__ __forceinline__ unsigned s2u(const void* p) {
    return (unsigned)__cvta_generic_to_shared(p);
}
__device__ __forceinline__ void cp16(void* dst, const void* src) {
    asm volatile("cp.async.cg.shared.global [%0], [%1], 16;"
                 :: "r"(s2u(dst)), "l"(src));
}
__device__ __forceinline__ void ldsm4(unsigned* r, unsigned addr) {
    asm volatile("ldmatrix.sync.aligned.m8n8.x4.shared.b16 {%0,%1,%2,%3}, [%4];"
                 : "=r"(r[0]), "=r"(r[1]), "=r"(r[2]), "=r"(r[3]) : "r"(addr));
}
__device__ __forceinline__ void ldsm2(unsigned* r, unsigned addr) {
    asm volatile("ldmatrix.sync.aligned.m8n8.x2.shared.b16 {%0,%1}, [%2];"
                 : "=r"(r[0]), "=r"(r[1]) : "r"(addr));
}
__device__ __forceinline__ void mma_s8(int* d, const unsigned* a, unsigned b0, unsigned b1) {
    asm volatile(
        "mma.sync.aligned.m16n8k32.row.col.s32.s8.s8.s32 "
        "{%0,%1,%2,%3}, {%4,%5,%6,%7}, {%8,%9}, {%0,%1,%2,%3};"
        : "+r"(d[0]), "+r"(d[1]), "+r"(d[2]), "+r"(d[3])
        : "r"(a[0]), "r"(a[1]), "r"(a[2]), "r"(a[3]), "r"(b0), "r"(b1));
}

// ---------------- zero per-launch scratch ----------------
__global__ void fm_zero() {
    int i = blockIdx.x * blockDim.x + threadIdx.x;
    if (i < BB * FF) g_xv[i] = 0.f;
    if (i < BB)      g_xc[i] = 0.f;
    if (i < 65)      g_maxb[i] = 0;
}

// ---------------- pass 1: per-column max |V|, max |c| ----------------
__global__ void fm_scale1(const float* __restrict__ V, const float* __restrict__ bias) {
    __shared__ int smax[65];
    int tid = threadIdx.x, lane = tid & 31;
    if (tid < 65) smax[tid] = 0;
    __syncthreads();
    int r = blockIdx.x * 256 + tid;
    float4 m4[16];
    float cabs = 0.f;
    if (r < VOCABN) {
        const float4* vr = (const float4*)(V + (size_t)r * 64);
        float ss = 0.f;
        #pragma unroll
        for (int j = 0; j < 16; j++) {
            float4 v = vr[j];
            ss += v.x*v.x + v.y*v.y + v.z*v.z + v.w*v.w;
            m4[j] = make_float4(fabsf(v.x), fabsf(v.y), fabsf(v.z), fabsf(v.w));
        }
        cabs = fabsf(bias[r] - 0.5f * ss);
    } else {
        #pragma unroll
        for (int j = 0; j < 16; j++) m4[j] = make_float4(0.f, 0.f, 0.f, 0.f);
    }
    #pragma unroll
    for (int j = 0; j < 16; j++) {
        float vx = m4[j].x, vy = m4[j].y, vz = m4[j].z, vw = m4[j].w;
        #pragma unroll
        for (int off = 16; off > 0; off >>= 1) {
            vx = fmaxf(vx, __shfl_xor_sync(0xFFFFFFFFu, vx, off));
            vy = fmaxf(vy, __shfl_xor_sync(0xFFFFFFFFu, vy, off));
            vz = fmaxf(vz, __shfl_xor_sync(0xFFFFFFFFu, vz, off));
            vw = fmaxf(vw, __shfl_xor_sync(0xFFFFFFFFu, vw, off));
        }
        if (lane == 0) {
            atomicMax(&smax[j*4+0], __float_as_int(vx));
            atomicMax(&smax[j*4+1], __float_as_int(vy));
            atomicMax(&smax[j*4+2], __float_as_int(vz));
            atomicMax(&smax[j*4+3], __float_as_int(vw));
        }
    }
    #pragma unroll
    for (int off = 16; off > 0; off >>= 1)
        cabs = fmaxf(cabs, __shfl_xor_sync(0xFFFFFFFFu, cabs, off));
    if (lane == 0) atomicMax(&smax[64], __float_as_int(cabs));
    __syncthreads();
    if (tid < 65) atomicMax(&g_maxb[tid], smax[tid]);
}

__global__ void fm_scale2() {
    int n = threadIdx.x;
    if (n < 65) {
        float m = __int_as_float(g_maxb[n]);
        float s = (m > 0.f) ? 127.f / m : 1.f;
        g_s[n] = s;
        g_inv[n] = 1.f / (256.f * s);
    }
}

// ---------------- pass 2: quantize B = [V | bias-0.5||v||^2 | 0] -> two s8 limbs, K-major ----------------
__global__ void fm_prep(const float* __restrict__ V, const float* __restrict__ bias) {
    __shared__ float sm[64][65];
    __shared__ float cs[64];
    int i0 = blockIdx.x * 64;
    int tid = threadIdx.x;
    for (int idx = tid; idx < 64 * 64; idx += 256) {
        int i = idx >> 6, f = idx & 63;
        int gi = i0 + i;
        sm[i][f] = (gi < VOCABN) ? V[(size_t)gi * 64 + f] : 0.f;
    }
    __syncthreads();
    if (tid < 64) {
        float ssum = 0.f;
        #pragma unroll
        for (int f = 0; f < 64; f++) { float v = sm[tid][f]; ssum += v * v; }
        int gi = i0 + tid;
        float b = (gi < VOCABN) ? bias[gi] : 0.f;
        cs[tid] = (gi < VOCABN) ? (b - 0.5f * ssum) : 0.f;
    }
    __syncthreads();
    for (int idx = tid; idx < 64 * 64; idx += 256) {
        int f = idx >> 6, i = idx & 63;
        float q = sm[i][f] * g_s[f];
        float h = rintf(q);
        float l = rintf((q - h) * 256.f);
        if (l > 127.f) l = 127.f;
        g_Bh8[(size_t)f * K_PAD + i0 + i] = (signed char)(int)h;
        g_Bl8[(size_t)f * K_PAD + i0 + i] = (signed char)(int)l;
    }
    if (tid < 64) {
        float q = cs[tid] * g_s[64];
        float h = rintf(q);
        float l = rintf((q - h) * 256.f);
        if (l > 127.f) l = 127.f;
        g_Bh8[(size_t)64 * K_PAD + i0 + tid] = (signed char)(int)h;
        g_Bl8[(size_t)64 * K_PAD + i0 + tid] = (signed char)(int)l;
    }
}

// ---------------- main: split-K s8 GEMM, exact s32 accumulation ----------------
__global__ void __launch_bounds__(128, 2) fm_main(const int* __restrict__ x) {
    __shared__ __align__(16) signed char sB[2][2][NB][BROW8];   // 41.5KB

    const int tid  = threadIdx.x;
    const int w    = tid >> 5;
    const int lane = tid & 31;
    const int gid  = lane >> 2;
    const int t4   = (lane & 3) * 4;
    const int t2   = (lane & 3) * 2;
    const int mt   = blockIdx.x & (M_TILES - 1);
    const int ks   = blockIdx.x >> 5;
    const int m0   = mt * 128;
    const int k0   = ks * K_PER;

    const int* xr[4];
    bool nl[4];
    #pragma unroll
    for (int j = 0; j < 4; j++) {
        int r = m0 + w * 32 + j * 8 + gid;
        xr[j] = x + (size_t)r * VOCABN;
        nl[j] = (r != BB - 1);
    }

    int accH[9][2][4], accL[9][2][4];
    #pragma unroll
    for (int n = 0; n < 9; n++)
        #pragma unroll
        for (int m = 0; m < 2; m++)
            #pragma unroll
            for (int i = 0; i < 4; i++) { accH[n][m][i] = 0; accL[n][m][i] = 0; }

    // stage k128 of both limbs: 2*72*8 = 1152 16B chunks, 9/thread
    auto stageB = [&](int st, int k) {
        #pragma unroll
        for (int j = 0; j < 9; j++) {
            int c = tid + j * 128;
            int limb = (c >= 576) ? 1 : 0;
            int cc = c - limb * 576;
            int n = cc >> 3, ch = cc & 7;
            const signed char* g = limb ? g_Bl8 : g_Bh8;
            cp16(&sB[st][limb][n][ch * 16], g + (size_t)n * K_PAD + k + ch * 16);
        }
        asm volatile("cp.async.commit_group;");
    };

    int4 raw[8];
    unsigned pa[8];   // [mf*4 + q]: a-regs for 2 mfrags, one k32 step
    auto loadA = [&](int cb) {
        #pragma unroll
        for (int mf = 0; mf < 2; mf++)
            #pragma unroll
            for (int q = 0; q < 4; q++) {
                const int* p = xr[mf * 2 + (q & 1)];
                int c = cb + (q >> 1) * 16 + t4;
                bool ok = nl[mf * 2 + (q & 1)] | (c < VOCABN);
                raw[mf * 4 + q] = ok ? *(const int4*)(p + c) : make_int4(0, 0, 0, 0);
            }
    };
    auto packA = [&]() {
        #pragma unroll
        for (int i = 0; i < 8; i++) {
            int4 v = raw[i];
            pa[i] = (unsigned)v.x | ((unsigned)v.y << 8)
                  | ((unsigned)v.z << 16) | ((unsigned)v.w << 24);
        }
    };

    const unsigned offX4 = (unsigned)((lane & 15) * BROW8 + (lane >> 4) * 16);
    const unsigned offX2 = (unsigned)((lane & 7) * BROW8 + ((lane >> 3) & 1) * 16);
    const unsigned sb0 = s2u(&sB[0][0][0][0]);

    auto doLimb = [&](unsigned lb, int (&acc)[9][2][4]) {
        #pragma unroll
        for (int j = 0; j < 4; j++) {
            unsigned bm[4];
            ldsm4(bm, lb + (unsigned)j * (16 * BROW8) + offX4);
            #pragma unroll
            for (int mf = 0; mf < 2; mf++) {
                mma_s8(acc[2 * j][mf],     pa + mf * 4, bm[0], bm[2]);
                mma_s8(acc[2 * j + 1][mf], pa + mf * 4, bm[1], bm[3]);
            }
        }
        unsigned b2[2];
        ldsm2(b2, lb + 64 * BROW8 + offX2);
        #pragma unroll
        for (int mf = 0; mf < 2; mf++)
            mma_s8(acc[8][mf], pa + mf * 4, b2[0], b2[1]);
    };

    stageB(0, k0);
    loadA(k0);

    for (int it = 0; it < ITERS; it++) {
        const int p = it & 1;
        __syncthreads();                       // prior reads of stage p^1 done
        if (it + 1 < ITERS) {
            stageB(p ^ 1, k0 + (it + 1) * TILE_K);
            asm volatile("cp.async.wait_group 1;");
        } else {
            asm volatile("cp.async.wait_group 0;");
        }
        __syncthreads();                       // stage p visible

        const unsigned stb = sb0 + (unsigned)p * (2 * LIMB_B);
        #pragma unroll
        for (int s = 0; s < 4; s++) {
            packA();
            loadA(k0 + it * TILE_K + (s + 1) * 32);   // prefetch next k32
            doLimb(stb + (unsigned)s * 32, accH);
            doLimb(stb + LIMB_B + (unsigned)s * 32, accL);
        }
    }

    // ---- epilogue: dequant + split-K accumulate ----
    #pragma unroll
    for (int mf = 0; mf < 2; mf++) {
        int rowA = m0 + w * 32 + mf * 16 + gid;
        #pragma unroll
        for (int nf = 0; nf < 8; nf++) {
            #pragma unroll
            for (int cc = 0; cc < 2; cc++) {
                int n = nf * 8 + t2 + cc;
                double inv = (double)g_inv[n];
                float v0 = (float)((double)(256LL * accH[nf][mf][cc]     + accL[nf][mf][cc])     * inv);
                float v1 = (float)((double)(256LL * accH[nf][mf][2 + cc] + accL[nf][mf][2 + cc]) * inv);
                atomicAdd(&g_xv[(size_t)rowA * FF + n],       v0);
                atomicAdd(&g_xv[(size_t)(rowA + 8) * FF + n], v1);
            }
        }
        if (t2 == 0) {   // c column (n = 64)
            double inv = (double)g_inv[64];
            atomicAdd(&g_xc[rowA],
                      (float)((double)(256LL * accH[8][mf][0] + accL[8][mf][0]) * inv));
            atomicAdd(&g_xc[rowA + 8],
                      (float)((double)(256LL * accH[8][mf][2] + accL[8][mf][2]) * inv));
        }
    }
}

// ---------------- finalize: out = g_bias + xc + 0.5 * ||xv||^2 ----------------
__global__ void fm_fin(const float* __restrict__ gb, float* __restrict__ out) {
    int b = blockIdx.x * blockDim.x + threadIdx.x;
    if (b >= BB) return;
    const float4* v = (const float4*)&g_xv[(size_t)b * FF];
    float ss = 0.f;
    #pragma unroll
    for (int i = 0; i < 16; i++) {
        float4 t = v[i];
        ss += t.x * t.x + t.y * t.y + t.z * t.z + t.w * t.w;
    }
    out[b] = gb[0] + g_xc[b] + 0.5f * ss;
}

extern "C" void kernel_launch(void* const* d_in, const int* in_sizes, int n_in,
                              void* d_out, int out_size) {
    const int*   x    = (const int*)d_in[0];
    const float* V    = (const float*)d_in[1];
    const float* bias = (const float*)d_in[2];
    const float* gb   = (const float*)d_in[3];
    float* out = (float*)d_out;
    (void)in_sizes; (void)n_in; (void)out_size;

    fm_zero<<<(BB * FF + 255) / 256, 256>>>();
    fm_scale1<<<196, 256>>>(V, bias);
    fm_scale2<<<1, 65>>>();
    fm_prep<<<K_PAD / 64, 256>>>(V, bias);
    fm_main<<<M_TILES * K_SPLITS, 128>>>(x);
    fm_fin<<<(BB + 255) / 256, 256>>>(gb, out);
}

// round 7
// speedup vs baseline: 1.7168x; 1.1695x over previous
#include <cuda_runtime.h>

#define BB       4096
#define VOCABN   50000
#define FF       64
#define K_PAD    50688       // 9 * 5632, B zero-padded beyond 50000
#define K_SPLITS 9
#define K_PER    5632        // 44 * 128
#define ITERS    44
#define TILE_K   128
#define M_TILES  32
#define NB       64          // V cols only; c handled via dp4a
#define BROW8    144         // int8 smem row stride (128 data + 16 pad)
#define LIMB_B   (NB * BROW8)   // 9216 bytes per limb per stage

// ---- device-global scratch (zero-initialized) ----
__device__ __align__(16) signed char g_Bh8[NB * K_PAD];
__device__ __align__(16) signed char g_Bl8[NB * K_PAD];
__device__ __align__(16) signed char g_ch8[K_PAD];
__device__ __align__(16) signed char g_cl8[K_PAD];
__device__ float g_xv[BB * FF];
__device__ float g_xc[BB];
__device__ int   g_maxb[65];
__device__ float g_s[65];
__device__ float g_inv[65];

__device__ __forceinline__ unsigned s2u(const void* p) {
    return (unsigned)__cvta_generic_to_shared(p);
}
__device__ __forceinline__ void cp16(void* dst, const void* src) {
    asm volatile("cp.async.cg.shared.global [%0], [%1], 16;"
                 :: "r"(s2u(dst)), "l"(src));
}
__device__ __forceinline__ void ldsm4(unsigned* r, unsigned addr) {
    asm volatile("ldmatrix.sync.aligned.m8n8.x4.shared.b16 {%0,%1,%2,%3}, [%4];"
                 : "=r"(r[0]), "=r"(r[1]), "=r"(r[2]), "=r"(r[3]) : "r"(addr));
}
__device__ __forceinline__ void mma_s8(int* d, const unsigned* a, unsigned b0, unsigned b1) {
    asm volatile(
        "mma.sync.aligned.m16n8k32.row.col.s32.s8.s8.s32 "
        "{%0,%1,%2,%3}, {%4,%5,%6,%7}, {%8,%9}, {%0,%1,%2,%3};"
        : "+r"(d[0]), "+r"(d[1]), "+r"(d[2]), "+r"(d[3])
        : "r"(a[0]), "r"(a[1]), "r"(a[2]), "r"(a[3]), "r"(b0), "r"(b1));
}

// ---------------- zero per-launch scratch ----------------
__global__ void fm_zero() {
    int i = blockIdx.x * blockDim.x + threadIdx.x;
    if (i < BB * FF) g_xv[i] = 0.f;
    if (i < BB)      g_xc[i] = 0.f;
    if (i < 65)      g_maxb[i] = 0;
}

// ---------------- pass 1: per-column max |V|, max |c| ----------------
__global__ void fm_scale1(const float* __restrict__ V, const float* __restrict__ bias) {
    __shared__ int smax[65];
    int tid = threadIdx.x, lane = tid & 31;
    if (tid < 65) smax[tid] = 0;
    __syncthreads();
    int r = blockIdx.x * 256 + tid;
    float4 m4[16];
    float cabs = 0.f;
    if (r < VOCABN) {
        const float4* vr = (const float4*)(V + (size_t)r * 64);
        float ss = 0.f;
        #pragma unroll
        for (int j = 0; j < 16; j++) {
            float4 v = vr[j];
            ss += v.x*v.x + v.y*v.y + v.z*v.z + v.w*v.w;
            m4[j] = make_float4(fabsf(v.x), fabsf(v.y), fabsf(v.z), fabsf(v.w));
        }
        cabs = fabsf(bias[r] - 0.5f * ss);
    } else {
        #pragma unroll
        for (int j = 0; j < 16; j++) m4[j] = make_float4(0.f, 0.f, 0.f, 0.f);
    }
    #pragma unroll
    for (int j = 0; j < 16; j++) {
        float vx = m4[j].x, vy = m4[j].y, vz = m4[j].z, vw = m4[j].w;
        #pragma unroll
        for (int off = 16; off > 0; off >>= 1) {
            vx = fmaxf(vx, __shfl_xor_sync(0xFFFFFFFFu, vx, off));
            vy = fmaxf(vy, __shfl_xor_sync(0xFFFFFFFFu, vy, off));
            vz = fmaxf(vz, __shfl_xor_sync(0xFFFFFFFFu, vz, off));
            vw = fmaxf(vw, __shfl_xor_sync(0xFFFFFFFFu, vw, off));
        }
        if (lane == 0) {
            atomicMax(&smax[j*4+0], __float_as_int(vx));
            atomicMax(&smax[j*4+1], __float_as_int(vy));
            atomicMax(&smax[j*4+2], __float_as_int(vz));
            atomicMax(&smax[j*4+3], __float_as_int(vw));
        }
    }
    #pragma unroll
    for (int off = 16; off > 0; off >>= 1)
        cabs = fmaxf(cabs, __shfl_xor_sync(0xFFFFFFFFu, cabs, off));
    if (lane == 0) atomicMax(&smax[64], __float_as_int(cabs));
    __syncthreads();
    if (tid < 65) atomicMax(&g_maxb[tid], smax[tid]);
}

__global__ void fm_scale2() {
    int n = threadIdx.x;
    if (n < 65) {
        float m = __int_as_float(g_maxb[n]);
        float s = (m > 0.f) ? 127.f / m : 1.f;
        g_s[n] = s;
        g_inv[n] = 1.f / (256.f * s);
    }
}

__device__ __forceinline__ void quant2(float v, float s, signed char& h8, signed char& l8) {
    float q = v * s;
    float h = rintf(q);
    float l = rintf((q - h) * 256.f);
    if (l > 127.f) l = 127.f;
    h8 = (signed char)(int)h;
    l8 = (signed char)(int)l;
}

// ---------------- pass 2: quantize V cols + c into s8 limbs, K-major ----------------
__global__ void fm_prep(const float* __restrict__ V, const float* __restrict__ bias) {
    __shared__ float sm[64][65];
    __shared__ float cs[64];
    int i0 = blockIdx.x * 64;
    int tid = threadIdx.x;
    for (int idx = tid; idx < 64 * 64; idx += 256) {
        int i = idx >> 6, f = idx & 63;
        int gi = i0 + i;
        sm[i][f] = (gi < VOCABN) ? V[(size_t)gi * 64 + f] : 0.f;
    }
    __syncthreads();
    if (tid < 64) {
        float ssum = 0.f;
        #pragma unroll
        for (int f = 0; f < 64; f++) { float v = sm[tid][f]; ssum += v * v; }
        int gi = i0 + tid;
        cs[tid] = (gi < VOCABN) ? (bias[gi] - 0.5f * ssum) : 0.f;
    }
    __syncthreads();
    for (int idx = tid; idx < 64 * 16; idx += 256) {
        int f = idx >> 4, i4 = (idx & 15) * 4;
        float s = g_s[f];
        char4 h4, l4;
        quant2(sm[i4 + 0][f], s, (signed char&)h4.x, (signed char&)l4.x);
        quant2(sm[i4 + 1][f], s, (signed char&)h4.y, (signed char&)l4.y);
        quant2(sm[i4 + 2][f], s, (signed char&)h4.z, (signed char&)l4.z);
        quant2(sm[i4 + 3][f], s, (signed char&)h4.w, (signed char&)l4.w);
        *(char4*)&g_Bh8[(size_t)f * K_PAD + i0 + i4] = h4;
        *(char4*)&g_Bl8[(size_t)f * K_PAD + i0 + i4] = l4;
    }
    if (tid < 64) {
        signed char h8, l8;
        quant2(cs[tid], g_s[64], h8, l8);
        g_ch8[i0 + tid] = h8;
        g_cl8[i0 + tid] = l8;
    }
}

// ---------------- main: split-K s8 GEMM (exact s32) + dp4a linear term ----------------
__global__ void __launch_bounds__(128, 2) fm_main(const int* __restrict__ x) {
    __shared__ __align__(16) signed char sB[2][2][NB][BROW8];   // 36.9KB
    __shared__ __align__(16) signed char sC[2][2][128];          // 512B

    const int tid  = threadIdx.x;
    const int w    = tid >> 5;
    const int lane = tid & 31;
    const int gid  = lane >> 2;
    const int t4   = (lane & 3) * 4;
    const int t2   = (lane & 3) * 2;
    const int mt   = blockIdx.x & (M_TILES - 1);
    const int ks   = blockIdx.x >> 5;
    const int m0   = mt * 128;
    const int k0   = ks * K_PER;

    const int* xr[4];
    bool nl[4];
    #pragma unroll
    for (int j = 0; j < 4; j++) {
        int r = m0 + w * 32 + j * 8 + gid;
        xr[j] = x + (size_t)r * VOCABN;
        nl[j] = (r != BB - 1);
    }

    int accH[8][2][4], accL[8][2][4];
    #pragma unroll
    for (int n = 0; n < 8; n++)
        #pragma unroll
        for (int m = 0; m < 2; m++)
            #pragma unroll
            for (int i = 0; i < 4; i++) { accH[n][m][i] = 0; accL[n][m][i] = 0; }
    int cH[4] = {0, 0, 0, 0}, cL[4] = {0, 0, 0, 0};

    // stage k128: B = 2*64*8 = 1024 chunks (8/thread); c = 16 chunks
    auto stageB = [&](int st, int k) {
        #pragma unroll
        for (int j = 0; j < 8; j++) {
            int c = tid + j * 128;
            int limb = (c >= 512) ? 1 : 0;
            int cc = c - limb * 512;
            int n = cc >> 3, ch = cc & 7;
            const signed char* g = limb ? g_Bl8 : g_Bh8;
            cp16(&sB[st][limb][n][ch * 16], g + (size_t)n * K_PAD + k + ch * 16);
        }
        if (tid < 16) {
            int limb = tid >> 3, ch = tid & 7;
            const signed char* g = limb ? g_cl8 : g_ch8;
            cp16(&sC[st][limb][ch * 16], g + k + ch * 16);
        }
        asm volatile("cp.async.commit_group;");
    };

    int4 raw[8];
    unsigned pa[8];
    auto loadA = [&](int cb) {
        #pragma unroll
        for (int mf = 0; mf < 2; mf++)
            #pragma unroll
            for (int q = 0; q < 4; q++) {
                const int* p = xr[mf * 2 + (q & 1)];
                int c = cb + (q >> 1) * 16 + t4;
                bool ok = nl[mf * 2 + (q & 1)] | (c < VOCABN);
                raw[mf * 4 + q] = ok ? *(const int4*)(p + c) : make_int4(0, 0, 0, 0);
            }
    };
    auto packA = [&]() {
        #pragma unroll
        for (int i = 0; i < 8; i++) {
            int4 v = raw[i];
            pa[i] = (unsigned)v.x | ((unsigned)v.y << 8)
                  | ((unsigned)v.z << 16) | ((unsigned)v.w << 24);
        }
    };

    const unsigned offX4 = (unsigned)((lane & 15) * BROW8 + (lane >> 4) * 16);
    const unsigned sb0 = s2u(&sB[0][0][0][0]);

    auto doLimb = [&](unsigned lb, int (&acc)[8][2][4]) {
        #pragma unroll
        for (int j = 0; j < 4; j++) {
            unsigned bm[4];
            ldsm4(bm, lb + (unsigned)j * (16 * BROW8) + offX4);
            #pragma unroll
            for (int mf = 0; mf < 2; mf++) {
                mma_s8(acc[2 * j][mf],     pa + mf * 4, bm[0], bm[2]);
                mma_s8(acc[2 * j + 1][mf], pa + mf * 4, bm[1], bm[3]);
            }
        }
    };

    stageB(0, k0);
    loadA(k0);

    for (int it = 0; it < ITERS; it++) {
        const int p = it & 1;
        __syncthreads();
        if (it + 1 < ITERS) {
            stageB(p ^ 1, k0 + (it + 1) * TILE_K);
            asm volatile("cp.async.wait_group 1;");
        } else {
            asm volatile("cp.async.wait_group 0;");
        }
        __syncthreads();

        const unsigned stb = sb0 + (unsigned)p * (2 * LIMB_B);
        #pragma unroll
        for (int s = 0; s < 4; s++) {
            packA();
            loadA(k0 + it * TILE_K + (s + 1) * 32);
            // linear (c) term via dp4a on ALU pipe
            {
                int w0h = *(const int*)&sC[p][0][s * 32 + t4];
                int w1h = *(const int*)&sC[p][0][s * 32 + 16 + t4];
                int w0l = *(const int*)&sC[p][1][s * 32 + t4];
                int w1l = *(const int*)&sC[p][1][s * 32 + 16 + t4];
                cH[0] = __dp4a((int)pa[0], w0h, cH[0]);
                cH[1] = __dp4a((int)pa[1], w0h, cH[1]);
                cH[0] = __dp4a((int)pa[2], w1h, cH[0]);
                cH[1] = __dp4a((int)pa[3], w1h, cH[1]);
                cH[2] = __dp4a((int)pa[4], w0h, cH[2]);
                cH[3] = __dp4a((int)pa[5], w0h, cH[3]);
                cH[2] = __dp4a((int)pa[6], w1h, cH[2]);
                cH[3] = __dp4a((int)pa[7], w1h, cH[3]);
                cL[0] = __dp4a((int)pa[0], w0l, cL[0]);
                cL[1] = __dp4a((int)pa[1], w0l, cL[1]);
                cL[0] = __dp4a((int)pa[2], w1l, cL[0]);
                cL[1] = __dp4a((int)pa[3], w1l, cL[1]);
                cL[2] = __dp4a((int)pa[4], w0l, cL[2]);
                cL[3] = __dp4a((int)pa[5], w0l, cL[3]);
                cL[2] = __dp4a((int)pa[6], w1l, cL[2]);
                cL[3] = __dp4a((int)pa[7], w1l, cL[3]);
            }
            doLimb(stb + (unsigned)s * 32, accH);
            doLimb(stb + LIMB_B + (unsigned)s * 32, accL);
        }
    }

    // ---- epilogue: dequant + split-K accumulate ----
    #pragma unroll
    for (int mf = 0; mf < 2; mf++) {
        int rowA = m0 + w * 32 + mf * 16 + gid;
        #pragma unroll
        for (int nf = 0; nf < 8; nf++) {
            #pragma unroll
            for (int cc = 0; cc < 2; cc++) {
                int n = nf * 8 + t2 + cc;
                double inv = (double)g_inv[n];
                float v0 = (float)((double)(256LL * accH[nf][mf][cc]     + accL[nf][mf][cc])     * inv);
                float v1 = (float)((double)(256LL * accH[nf][mf][2 + cc] + accL[nf][mf][2 + cc]) * inv);
                atomicAdd(&g_xv[(size_t)rowA * FF + n],       v0);
                atomicAdd(&g_xv[(size_t)(rowA + 8) * FF + n], v1);
            }
        }
    }
    // c term: quad-reduce (lanes sharing gid) then one atomic per row slot
    #pragma unroll
    for (int j = 0; j < 4; j++) {
        int h = cH[j], l = cL[j];
        h += __shfl_xor_sync(0xFFFFFFFFu, h, 1);
        h += __shfl_xor_sync(0xFFFFFFFFu, h, 2);
        l += __shfl_xor_sync(0xFFFFFFFFu, l, 1);
        l += __shfl_xor_sync(0xFFFFFFFFu, l, 2);
        if ((lane & 3) == 0) {
            int row = m0 + w * 32 + j * 8 + gid;
            atomicAdd(&g_xc[row],
                      (float)((double)(256LL * h + l) * (double)g_inv[64]));
        }
    }
}

// ---------------- finalize: 4 threads/row + quad reduce ----------------
__global__ void fm_fin(const float* __restrict__ gb, float* __restrict__ out) {
    int t = blockIdx.x * blockDim.x + threadIdx.x;   // 16384 threads
    int b = t >> 2, part = t & 3;
    const float4* v = (const float4*)&g_xv[(size_t)b * FF + part * 16];
    float ss = 0.f;
    #pragma unroll
    for (int i = 0; i < 4; i++) {
        float4 q = v[i];
        ss += q.x * q.x + q.y * q.y + q.z * q.z + q.w * q.w;
    }
    ss += __shfl_xor_sync(0xFFFFFFFFu, ss, 1);
    ss += __shfl_xor_sync(0xFFFFFFFFu, ss, 2);
    if (part == 0) out[b] = gb[0] + g_xc[b] + 0.5f * ss;
}

extern "C" void kernel_launch(void* const* d_in, const int* in_sizes, int n_in,
                              void* d_out, int out_size) {
    const int*   x    = (const int*)d_in[0];
    const float* V    = (const float*)d_in[1];
    const float* bias = (const float*)d_in[2];
    const float* gb   = (const float*)d_in[3];
    float* out = (float*)d_out;
    (void)in_sizes; (void)n_in; (void)out_size;

    fm_zero<<<(BB * FF + 255) / 256, 256>>>();
    fm_scale1<<<196, 256>>>(V, bias);
    fm_scale2<<<1, 65>>>();
    fm_prep<<<K_PAD / 64, 256>>>(V, bias);
    fm_main<<<M_TILES * K_SPLITS, 128>>>(x);
    fm_fin<<<64, 256>>>(gb, out);
}

// round 9
// speedup vs baseline: 1.8252x; 1.0631x over previous
#include <cuda_runtime.h>

#define BB       4096
#define VOCABN   50000
#define FF       64
#define K_PAD    50688       // 9 * 5632, B zero-padded beyond 50000
#define K_SPLITS 9
#define K_PER    5632        // 44 * 128
#define ITERS    44
#define TILE_K   128
#define M_TILES  32
#define NB       64          // V cols only; c handled via dp4a
#define BROW8    144         // int8 smem row stride (128 data + 16 pad)
#define LIMB_B   (NB * BROW8)   // 9216 bytes per limb per stage

// ---- device-global scratch (zero-initialized) ----
__device__ __align__(16) signed char g_Bh8[NB * K_PAD];
__device__ __align__(16) signed char g_Bl8[NB * K_PAD];
__device__ __align__(16) signed char g_ch8[K_PAD];
__device__ __align__(16) signed char g_cl8[K_PAD];
__device__ float g_xv[BB * FF];
__device__ float g_xc[BB];
__device__ int   g_maxb[65];
__device__ float g_s[65];
__device__ float g_inv[65];

__device__ __forceinline__ unsigned s2u(const void* p) {
    return (unsigned)__cvta_generic_to_shared(p);
}
__device__ __forceinline__ void cp16(void* dst, const void* src) {
    asm volatile("cp.async.cg.shared.global [%0], [%1], 16;"
                 :: "r"(s2u(dst)), "l"(src));
}
__device__ __forceinline__ void ldsm4(unsigned* r, unsigned addr) {
    asm volatile("ldmatrix.sync.aligned.m8n8.x4.shared.b16 {%0,%1,%2,%3}, [%4];"
                 : "=r"(r[0]), "=r"(r[1]), "=r"(r[2]), "=r"(r[3]) : "r"(addr));
}
__device__ __forceinline__ void mma_s8(int* d, const unsigned* a, unsigned b0, unsigned b1) {
    asm volatile(
        "mma.sync.aligned.m16n8k32.row.col.s32.s8.s8.s32 "
        "{%0,%1,%2,%3}, {%4,%5,%6,%7}, {%8,%9}, {%0,%1,%2,%3};"
        : "+r"(d[0]), "+r"(d[1]), "+r"(d[2]), "+r"(d[3])
        : "r"(a[0]), "r"(a[1]), "r"(a[2]), "r"(a[3]), "r"(b0), "r"(b1));
}

// ---------------- zero per-launch scratch ----------------
__global__ void fm_zero() {
    int i = blockIdx.x * blockDim.x + threadIdx.x;
    if (i < BB * FF) g_xv[i] = 0.f;
    if (i < BB)      g_xc[i] = 0.f;
    if (i < 65)      g_maxb[i] = 0;
}

// ---------------- pass 1: per-column max |V|, max |c| ----------------
__global__ void fm_scale1(const float* __restrict__ V, const float* __restrict__ bias) {
    __shared__ int smax[65];
    int tid = threadIdx.x, lane = tid & 31;
    if (tid < 65) smax[tid] = 0;
    __syncthreads();
    int r = blockIdx.x * 256 + tid;
    float4 m4[16];
    float cabs = 0.f;
    if (r < VOCABN) {
        const float4* vr = (const float4*)(V + (size_t)r * 64);
        float ss = 0.f;
        #pragma unroll
        for (int j = 0; j < 16; j++) {
            float4 v = vr[j];
            ss += v.x*v.x + v.y*v.y + v.z*v.z + v.w*v.w;
            m4[j] = make_float4(fabsf(v.x), fabsf(v.y), fabsf(v.z), fabsf(v.w));
        }
        cabs = fabsf(bias[r] - 0.5f * ss);
    } else {
        #pragma unroll
        for (int j = 0; j < 16; j++) m4[j] = make_float4(0.f, 0.f, 0.f, 0.f);
    }
    #pragma unroll
    for (int j = 0; j < 16; j++) {
        float vx = m4[j].x, vy = m4[j].y, vz = m4[j].z, vw = m4[j].w;
        #pragma unroll
        for (int off = 16; off > 0; off >>= 1) {
            vx = fmaxf(vx, __shfl_xor_sync(0xFFFFFFFFu, vx, off));
            vy = fmaxf(vy, __shfl_xor_sync(0xFFFFFFFFu, vy, off));
            vz = fmaxf(vz, __shfl_xor_sync(0xFFFFFFFFu, vz, off));
            vw = fmaxf(vw, __shfl_xor_sync(0xFFFFFFFFu, vw, off));
        }
        if (lane == 0) {
            atomicMax(&smax[j*4+0], __float_as_int(vx));
            atomicMax(&smax[j*4+1], __float_as_int(vy));
            atomicMax(&smax[j*4+2], __float_as_int(vz));
            atomicMax(&smax[j*4+3], __float_as_int(vw));
        }
    }
    #pragma unroll
    for (int off = 16; off > 0; off >>= 1)
        cabs = fmaxf(cabs, __shfl_xor_sync(0xFFFFFFFFu, cabs, off));
    if (lane == 0) atomicMax(&smax[64], __float_as_int(cabs));
    __syncthreads();
    if (tid < 65) atomicMax(&g_maxb[tid], smax[tid]);
}

__global__ void fm_scale2() {
    int n = threadIdx.x;
    if (n < 65) {
        float m = __int_as_float(g_maxb[n]);
        float s = (m > 0.f) ? 127.f / m : 1.f;
        g_s[n] = s;
        g_inv[n] = 1.f / (256.f * s);
    }
}

__device__ __forceinline__ void quant2(float v, float s, signed char& h8, signed char& l8) {
    float q = v * s;
    float h = rintf(q);
    float l = rintf((q - h) * 256.f);
    if (l > 127.f) l = 127.f;
    h8 = (signed char)(int)h;
    l8 = (signed char)(int)l;
}

// ---------------- pass 2: quantize V cols + c into s8 limbs, K-major ----------------
__global__ void fm_prep(const float* __restrict__ V, const float* __restrict__ bias) {
    __shared__ float sm[64][65];
    __shared__ float cs[64];
    int i0 = blockIdx.x * 64;
    int tid = threadIdx.x;
    for (int idx = tid; idx < 64 * 64; idx += 256) {
        int i = idx >> 6, f = idx & 63;
        int gi = i0 + i;
        sm[i][f] = (gi < VOCABN) ? V[(size_t)gi * 64 + f] : 0.f;
    }
    __syncthreads();
    if (tid < 64) {
        float ssum = 0.f;
        #pragma unroll
        for (int f = 0; f < 64; f++) { float v = sm[tid][f]; ssum += v * v; }
        int gi = i0 + tid;
        cs[tid] = (gi < VOCABN) ? (bias[gi] - 0.5f * ssum) : 0.f;
    }
    __syncthreads();
    for (int idx = tid; idx < 64 * 16; idx += 256) {
        int f = idx >> 4, i4 = (idx & 15) * 4;
        float s = g_s[f];
        char4 h4, l4;
        quant2(sm[i4 + 0][f], s, (signed char&)h4.x, (signed char&)l4.x);
        quant2(sm[i4 + 1][f], s, (signed char&)h4.y, (signed char&)l4.y);
        quant2(sm[i4 + 2][f], s, (signed char&)h4.z, (signed char&)l4.z);
        quant2(sm[i4 + 3][f], s, (signed char&)h4.w, (signed char&)l4.w);
        *(char4*)&g_Bh8[(size_t)f * K_PAD + i0 + i4] = h4;
        *(char4*)&g_Bl8[(size_t)f * K_PAD + i0 + i4] = l4;
    }
    if (tid < 64) {
        signed char h8, l8;
        quant2(cs[tid], g_s[64], h8, l8);
        g_ch8[i0 + tid] = h8;
        g_cl8[i0 + tid] = l8;
    }
}

// ---------------- main: split-K s8 GEMM (exact s32) + dp4a linear term ----------------
__global__ void __launch_bounds__(128, 2) fm_main(const int* __restrict__ x) {
    __shared__ __align__(16) signed char sB[2][2][NB][BROW8];   // 36.9KB
    __shared__ __align__(16) signed char sC[2][2][128];          // 512B

    const int tid  = threadIdx.x;
    const int w    = tid >> 5;
    const int lane = tid & 31;
    const int gid  = lane >> 2;
    const int t4   = (lane & 3) * 4;
    const int t2   = (lane & 3) * 2;
    const int mt   = blockIdx.x & (M_TILES - 1);
    const int ks   = blockIdx.x >> 5;
    const int m0   = mt * 128;
    const int k0   = ks * K_PER;

    const int* xr[4];
    bool nl[4];
    #pragma unroll
    for (int j = 0; j < 4; j++) {
        int r = m0 + w * 32 + j * 8 + gid;
        xr[j] = x + (size_t)r * VOCABN;
        nl[j] = (r != BB - 1);
    }

    int accH[8][2][4], accL[8][2][4];
    #pragma unroll
    for (int n = 0; n < 8; n++)
        #pragma unroll
        for (int m = 0; m < 2; m++)
            #pragma unroll
            for (int i = 0; i < 4; i++) { accH[n][m][i] = 0; accL[n][m][i] = 0; }
    int cH[4] = {0, 0, 0, 0}, cL[4] = {0, 0, 0, 0};

    // stage k128: B = 2*64*8 = 1024 chunks (8/thread); c = 16 chunks
    auto stageB = [&](int st, int k) {
        #pragma unroll
        for (int j = 0; j < 8; j++) {
            int c = tid + j * 128;
            int limb = (c >= 512) ? 1 : 0;
            int cc = c - limb * 512;
            int n = cc >> 3, ch = cc & 7;
            const signed char* g = limb ? g_Bl8 : g_Bh8;
            cp16(&sB[st][limb][n][ch * 16], g + (size_t)n * K_PAD + k + ch * 16);
        }
        if (tid < 16) {
            int limb = tid >> 3, ch = tid & 7;
            const signed char* g = limb ? g_cl8 : g_ch8;
            cp16(&sC[st][limb][ch * 16], g + k + ch * 16);
        }
        asm volatile("cp.async.commit_group;");
    };

    // depth-2 A prefetch: raw[pb] loaded at step g, consumed at step g+2
    int4 raw[2][8];
    unsigned pa[8];
    auto loadA = [&](int pb, int cb) {
        #pragma unroll
        for (int mf = 0; mf < 2; mf++)
            #pragma unroll
            for (int q = 0; q < 4; q++) {
                const int* p = xr[mf * 2 + (q & 1)];
                int c = cb + (q >> 1) * 16 + t4;
                bool ok = nl[mf * 2 + (q & 1)] | (c < VOCABN);
                raw[pb][mf * 4 + q] = ok ? *(const int4*)(p + c) : make_int4(0, 0, 0, 0);
            }
    };
    auto packA = [&](int pb) {
        #pragma unroll
        for (int i = 0; i < 8; i++) {
            int4 v = raw[pb][i];
            pa[i] = (unsigned)v.x | ((unsigned)v.y << 8)
                  | ((unsigned)v.z << 16) | ((unsigned)v.w << 24);
        }
    };

    const unsigned offX4 = (unsigned)((lane & 15) * BROW8 + (lane >> 4) * 16);
    const unsigned sb0 = s2u(&sB[0][0][0][0]);

    auto doLimb = [&](unsigned lb, int (&acc)[8][2][4]) {
        #pragma unroll
        for (int j = 0; j < 4; j++) {
            unsigned bm[4];
            ldsm4(bm, lb + (unsigned)j * (16 * BROW8) + offX4);
            #pragma unroll
            for (int mf = 0; mf < 2; mf++) {
                mma_s8(acc[2 * j][mf],     pa + mf * 4, bm[0], bm[2]);
                mma_s8(acc[2 * j + 1][mf], pa + mf * 4, bm[1], bm[3]);
            }
        }
    };

    stageB(0, k0);
    loadA(0, k0);           // g = 0
    loadA(1, k0 + 32);      // g = 1

    for (int it = 0; it < ITERS; it++) {
        const int p = it & 1;
        __syncthreads();
        if (it + 1 < ITERS) {
            stageB(p ^ 1, k0 + (it + 1) * TILE_K);
            asm volatile("cp.async.wait_group 1;");
        } else {
            asm volatile("cp.async.wait_group 0;");
        }
        __syncthreads();

        const unsigned stb = sb0 + (unsigned)p * (2 * LIMB_B);
        #pragma unroll
        for (int s = 0; s < 4; s++) {
            const int g = it * 4 + s;
            const int pb = g & 1;
            packA(pb);                          // consume batch loaded at g-2
            loadA(pb, k0 + (g + 2) * 32);       // issue batch for g+2
            // linear (c) term via dp4a on ALU pipe
            {
                int w0h = *(const int*)&sC[p][0][s * 32 + t4];
                int w1h = *(const int*)&sC[p][0][s * 32 + 16 + t4];
                int w0l = *(const int*)&sC[p][1][s * 32 + t4];
                int w1l = *(const int*)&sC[p][1][s * 32 + 16 + t4];
                cH[0] = __dp4a((int)pa[0], w0h, cH[0]);
                cH[1] = __dp4a((int)pa[1], w0h, cH[1]);
                cH[0] = __dp4a((int)pa[2], w1h, cH[0]);
                cH[1] = __dp4a((int)pa[3], w1h, cH[1]);
                cH[2] = __dp4a((int)pa[4], w0h, cH[2]);
                cH[3] = __dp4a((int)pa[5], w0h, cH[3]);
                cH[2] = __dp4a((int)pa[6], w1h, cH[2]);
                cH[3] = __dp4a((int)pa[7], w1h, cH[3]);
                cL[0] = __dp4a((int)pa[0], w0l, cL[0]);
                cL[1] = __dp4a((int)pa[1], w0l, cL[1]);
                cL[0] = __dp4a((int)pa[2], w1l, cL[0]);
                cL[1] = __dp4a((int)pa[3], w1l, cL[1]);
                cL[2] = __dp4a((int)pa[4], w0l, cL[2]);
                cL[3] = __dp4a((int)pa[5], w0l, cL[3]);
                cL[2] = __dp4a((int)pa[6], w1l, cL[2]);
                cL[3] = __dp4a((int)pa[7], w1l, cL[3]);
            }
            doLimb(stb + (unsigned)s * 32, accH);
            doLimb(stb + LIMB_B + (unsigned)s * 32, accL);
        }
    }

    // ---- epilogue: dequant + split-K accumulate ----
    #pragma unroll
    for (int mf = 0; mf < 2; mf++) {
        int rowA = m0 + w * 32 + mf * 16 + gid;
        #pragma unroll
        for (int nf = 0; nf < 8; nf++) {
            #pragma unroll
            for (int cc = 0; cc < 2; cc++) {
                int n = nf * 8 + t2 + cc;
                double inv = (double)g_inv[n];
                float v0 = (float)((double)(256LL * accH[nf][mf][cc]     + accL[nf][mf][cc])     * inv);
                float v1 = (float)((double)(256LL * accH[nf][mf][2 + cc] + accL[nf][mf][2 + cc]) * inv);
                atomicAdd(&g_xv[(size_t)rowA * FF + n],       v0);
                atomicAdd(&g_xv[(size_t)(rowA + 8) * FF + n], v1);
            }
        }
    }
    // c term: quad-reduce then one atomic per row slot
    #pragma unroll
    for (int j = 0; j < 4; j++) {
        int h = cH[j], l = cL[j];
        h += __shfl_xor_sync(0xFFFFFFFFu, h, 1);
        h += __shfl_xor_sync(0xFFFFFFFFu, h, 2);
        l += __shfl_xor_sync(0xFFFFFFFFu, l, 1);
        l += __shfl_xor_sync(0xFFFFFFFFu, l, 2);
        if ((lane & 3) == 0) {
            int row = m0 + w * 32 + j * 8 + gid;
            atomicAdd(&g_xc[row],
                      (float)((double)(256LL * h + l) * (double)g_inv[64]));
        }
    }
}

// ---------------- finalize: 4 threads/row + quad reduce ----------------
__global__ void fm_fin(const float* __restrict__ gb, float* __restrict__ out) {
    int t = blockIdx.x * blockDim.x + threadIdx.x;   // 16384 threads
    int b = t >> 2, part = t & 3;
    const float4* v = (const float4*)&g_xv[(size_t)b * FF + part * 16];
    float ss = 0.f;
    #pragma unroll
    for (int i = 0; i < 4; i++) {
        float4 q = v[i];
        ss += q.x * q.x + q.y * q.y + q.z * q.z + q.w * q.w;
    }
    ss += __shfl_xor_sync(0xFFFFFFFFu, ss, 1);
    ss += __shfl_xor_sync(0xFFFFFFFFu, ss, 2);
    if (part == 0) out[b] = gb[0] + g_xc[b] + 0.5f * ss;
}

extern "C" void kernel_launch(void* const* d_in, const int* in_sizes, int n_in,
                              void* d_out, int out_size) {
    const int*   x    = (const int*)d_in[0];
    const float* V    = (const float*)d_in[1];
    const float* bias = (const float*)d_in[2];
    const float* gb   = (const float*)d_in[3];
    float* out = (float*)d_out;
    (void)in_sizes; (void)n_in; (void)out_size;

    fm_zero<<<(BB * FF + 255) / 256, 256>>>();
    fm_scale1<<<196, 256>>>(V, bias);
    fm_scale2<<<1, 65>>>();
    fm_prep<<<K_PAD / 64, 256>>>(V, bias);
    fm_main<<<M_TILES * K_SPLITS, 128>>>(x);
    fm_fin<<<64, 256>>>(gb, out);
}